// round 10
// baseline (speedup 1.0000x reference)
#include <cuda_runtime.h>
#include <cuda_bf16.h>
#include <cstdint>

// Shapes (fixed by the problem)
#define BB      8
#define TIMES   288
#define NNODES  207
#define DD      64
#define TT      288
#define NBT     (BB * TIMES)      // 2304 (b,t) rows
#define NV      (NNODES * DD / 4) // 3312 float4 per row

// Steady-state dur is pinned at ~26.1-26.9us by the 122 MB/replay DRAM write
// drain; all prior store-path variants leave L2 lines DIRTY, so replay N's
// writeback contends with replay N+1's fill inside the LTS. st.global.wt
// writes through (clean L2 lines -> free reallocation, no deferred writeback).
// Same total DRAM bytes; tests whether dirty-eviction scheduling costs
// anything on top of raw write bandwidth.
__device__ __forceinline__ void st_wt(float4* p, float4 v) {
    asm volatile("st.global.wt.v4.f32 [%0], {%1,%2,%3,%4};"
                 :: "l"(p), "f"(v.x), "f"(v.y), "f"(v.z), "f"(v.w) : "memory");
}

__global__ __launch_bounds__(256, 8)
void tememb_kernel(const int*   __restrict__ TE,
                   const float* __restrict__ W1,
                   const float* __restrict__ b1,
                   const float* __restrict__ W2,
                   const float* __restrict__ b2,
                   float*       __restrict__ out)
{
    const int bt  = blockIdx.x;     // 0 .. 2303
    const int tid = threadIdx.x;    // 0 .. 255

    __shared__ float h[DD];
    __shared__ float o[DD];

    // TE is (B, TIMES, N, 2); only node 0 matters (reference slices [:, :, 0, :]).
    const int* te = TE + (size_t)bt * (NNODES * 2);

    if (tid < DD) {
        int dow = te[0] % 7;  if (dow < 0) dow += 7;
        int tod = te[1] % TT; if (tod < 0) tod += TT;
        // one_hot(dow,7) ++ one_hot(tod,288) @ W1  ==  W1[dow] + W1[7+tod]
        float v = W1[dow * DD + tid] + W1[(7 + tod) * DD + tid] + b1[tid];
        h[tid] = v > 0.f ? v : 0.f;
    }
    __syncthreads();

    if (tid < DD) {
        float acc = b2[tid];
        #pragma unroll
        for (int d = 0; d < DD; ++d)
            acc = fmaf(h[d], W2[d * DD + tid], acc);   // coalesced W2 columns
        o[tid] = acc;
    }
    __syncthreads();

    // Broadcast the 64-float result to all 207 nodes (3312 float4 per row).
    // (tid + k*256) % 16 == tid % 16 -> each thread's source float4 is fixed.
    const float4 v4 = reinterpret_cast<const float4*>(o)[tid & 15];
    float4* __restrict__ dst = reinterpret_cast<float4*>(out) + (size_t)bt * NV;

    #pragma unroll 8
    for (int j = tid; j < NV; j += 256)
        st_wt(dst + j, v4);
}

extern "C" void kernel_launch(void* const* d_in, const int* in_sizes, int n_in,
                              void* d_out, int out_size)
{
    const int*   TE = (const int*)  d_in[0];
    const float* W1 = (const float*)d_in[1];
    const float* b1 = (const float*)d_in[2];
    const float* W2 = (const float*)d_in[3];
    const float* b2 = (const float*)d_in[4];
    float* out = (float*)d_out;

    tememb_kernel<<<NBT, 256>>>(TE, W1, b1, W2, b2, out);
}

// round 11
// speedup vs baseline: 1.0846x; 1.0846x over previous
#include <cuda_runtime.h>
#include <cuda_bf16.h>
#include <cstdint>

// Shapes (fixed by the problem)
#define BB      8
#define TIMES   288
#define NNODES  207
#define DD      64
#define TT      288
#define NBT     (BB * TIMES)      // 2304 (b,t) rows
#define NV8     (NNODES * DD / 8) // 1656 x 32B stores per row (52.9 KB)
#define RESIDENT_ROWS 1800        // ~95 MB hinted L2-resident, ~27 MB streamed

// FINAL (R11). Measured roofline across 10 rounds: steady-state dur is pinned
// at 26.1-26.9us by the DRAM write drain of the contractual 122 MB fp32 output
// (~4.6 TB/s write-only sustained). Every write path tested — STG.128 (unroll
// 4/8), st.cs, st.wt, 256-bit STG + evict_first/evict_last, TMA bulk stores,
// 256/512-thread blocks, 1/2 rows per block — ties within noise; in-kernel
// time (22.4-24.5us) is already below the drain floor. This variant posted the
// best measured dur (26.112us, R4): evict_last keeps resident-row lines
// re-dirtied in place, deferring part of the drain; tail rows stream.
struct v8 { uint32_t r[8]; };

__device__ __forceinline__ void st_evict_last(void* p, const v8& v) {
    asm volatile("st.global.L2::evict_last.v8.b32 [%0], {%1,%2,%3,%4,%5,%6,%7,%8};"
                 :: "l"(p), "r"(v.r[0]), "r"(v.r[1]), "r"(v.r[2]), "r"(v.r[3]),
                    "r"(v.r[4]), "r"(v.r[5]), "r"(v.r[6]), "r"(v.r[7]) : "memory");
}
__device__ __forceinline__ void st_evict_first(void* p, const v8& v) {
    asm volatile("st.global.L2::evict_first.v8.b32 [%0], {%1,%2,%3,%4,%5,%6,%7,%8};"
                 :: "l"(p), "r"(v.r[0]), "r"(v.r[1]), "r"(v.r[2]), "r"(v.r[3]),
                    "r"(v.r[4]), "r"(v.r[5]), "r"(v.r[6]), "r"(v.r[7]) : "memory");
}

__global__ __launch_bounds__(256, 8)
void tememb_kernel(const int*   __restrict__ TE,
                   const float* __restrict__ W1,
                   const float* __restrict__ b1,
                   const float* __restrict__ W2,
                   const float* __restrict__ b2,
                   float*       __restrict__ out)
{
    const int bt  = blockIdx.x;     // 0 .. 2303
    const int tid = threadIdx.x;    // 0 .. 255

    __shared__ float h[DD];
    __shared__ float o[DD];

    // TE is (B, TIMES, N, 2); only node 0 matters (reference slices [:, :, 0, :]).
    const int* te = TE + (size_t)bt * (NNODES * 2);

    if (tid < DD) {
        int dow = te[0] % 7;  if (dow < 0) dow += 7;
        int tod = te[1] % TT; if (tod < 0) tod += TT;
        // one_hot(dow,7) ++ one_hot(tod,288) @ W1  ==  W1[dow] + W1[7+tod]
        float v = W1[dow * DD + tid] + W1[(7 + tod) * DD + tid] + b1[tid];
        h[tid] = v > 0.f ? v : 0.f;
    }
    __syncthreads();

    if (tid < DD) {
        float acc = b2[tid];
        #pragma unroll
        for (int d = 0; d < DD; ++d)
            acc = fmaf(h[d], W2[d * DD + tid], acc);   // coalesced W2 columns
        o[tid] = acc;
    }
    __syncthreads();

    // Broadcast the 64-float result to all 207 nodes via 32B stores.
    // (j*8) % 64 == (tid&7)*8 for j = tid + k*256 -> fixed 32B source slice.
    v8 val;
    {
        const uint32_t* os = reinterpret_cast<const uint32_t*>(o) + (tid & 7) * 8;
        #pragma unroll
        for (int i = 0; i < 8; ++i) val.r[i] = os[i];
    }

    uint32_t* __restrict__ dst =
        reinterpret_cast<uint32_t*>(out) + (size_t)bt * (NNODES * DD);

    if (bt < RESIDENT_ROWS) {
        #pragma unroll 4
        for (int j = tid; j < NV8; j += 256)
            st_evict_last(dst + (size_t)j * 8, val);
    } else {
        #pragma unroll 4
        for (int j = tid; j < NV8; j += 256)
            st_evict_first(dst + (size_t)j * 8, val);
    }
}

extern "C" void kernel_launch(void* const* d_in, const int* in_sizes, int n_in,
                              void* d_out, int out_size)
{
    const int*   TE = (const int*)  d_in[0];
    const float* W1 = (const float*)d_in[1];
    const float* b1 = (const float*)d_in[2];
    const float* W2 = (const float*)d_in[3];
    const float* b2 = (const float*)d_in[4];
    float* out = (float*)d_out;

    tememb_kernel<<<NBT, 256>>>(TE, W1, b1, W2, b2, out);
}